// round 16
// baseline (speedup 1.0000x reference)
#include <cuda_runtime.h>
#include <math.h>
typedef unsigned long long ull;

#define Bn 16
#define Tn 1000
#define NT 128
#define TPB 512
#define NCHUNK 8
#define NBLK (Bn*NCHUNK)
#define GAMMA_F 1e-4f
#define BXT (Bn*8*Tn)

__device__ float g_hh[2][Bn][NCHUNK][2][48];
__device__ float g_xh[2][Bn][NCHUNK][2][8];
__device__ unsigned g_cnt;
__device__ volatile unsigned g_gen;

// shared layout (floats)
constexpr int WEP=0, WEF=4608, WYH=9216;
constexpr int W2P=11520, W2F=13824, W2Y=16128;
constexpr int WG=18432;
constexpr int WPM=32256, WFM=32640, WYM=33024, WDEC=33408;
constexpr int B1P=33792, B1F=33840, B2S=33888, BIH=33936, BHH=34080, BDEC=34224;
constexpr int SQI=34232, SQIF=34296, SFTQI=34360, SFTQIF=34424, SHTRIH=34488;
constexpr int HLo=34552, HRo=34600;
constexpr int BUF0=34648;           // 48x128
constexpr int XSH=40792;            // 8x130 halo
constexpr int MPo=41832, MFo=42856, MYo=43880;
constexpr int BUF1=44904, SCR=51048; // 48x128 each
constexpr int SMEM_FLOATS=57192;
constexpr int SMEM_BYTES=SMEM_FLOATS*4;  // 228,768 B

__device__ __forceinline__ ull pack2(float a, float b){ull r;asm("mov.b64 %0,{%1,%2};":"=l"(r):"f"(a),"f"(b));return r;}
__device__ __forceinline__ void unpack2(ull v, float&a, float&b){asm("mov.b64 {%0,%1},%2;":"=f"(a),"=f"(b):"l"(v));}
__device__ __forceinline__ ull fma2(ull a, ull b, ull c){ull d;asm("fma.rn.f32x2 %0,%1,%2,%3;":"=l"(d):"l"(a),"l"(b),"l"(c));return d;}
__device__ __forceinline__ ull add2(ull a, ull b){ull d;asm("add.rn.f32x2 %0,%1,%2;":"=l"(d):"l"(a),"l"(b));return d;}
__device__ __forceinline__ float sigmf(float x){ return 1.f/(1.f+__expf(-x)); }
__device__ __forceinline__ float tanhfast(float x){ return 1.f - 2.f/(__expf(2.f*x)+1.f); }

__device__ __forceinline__ void msgphase(float* __restrict__ sm, float* __restrict__ xsh,
                                         int t0, int tid, float cy0, float cy1) {
    #pragma unroll
    for (int rep = 0; rep < 2; rep++) {
        int item = tid + rep*TPB;
        int i = item >> 7, n = item & 127, t = t0 + n;
        bool valid = t < Tn;
        float accp = 0.f, accf = 0.f;
        float accy = (rep == 0) ? cy0 : cy1;
        #pragma unroll
        for (int j = 0; j < 8; j++) {
            float xc = xsh[j*130 + 1 + n];
            accp = fmaf(-sm[SQI+i*8+j], xc, accp);
            accp = fmaf(sm[SQIF+i*8+j], xsh[j*130 + n], accp);
            accf = fmaf(sm[SFTQI+i*8+j], xsh[j*130 + 2 + n], accf);
            accf = fmaf(-sm[SFTQIF+i*8+j], xc, accf);
            accy = fmaf(-sm[SHTRIH+i*8+j], xc, accy);
        }
        sm[MPo + i*128+n] = (valid && t > 0) ? accp : 0.f;
        sm[MFo + i*128+n] = (t < Tn-1) ? accf : 0.f;
        sm[MYo + i*128+n] = valid ? accy : 0.f;
    }
}

// edge (past/fut): per-k center+neighbor quads; msg part uses k-pair quads
template<int SHIFT>
__device__ __forceinline__ void edge1pf(const float* __restrict__ sm, int WEo_, int WMo_,
    const float* __restrict__ msg, const float* __restrict__ hsh, float* __restrict__ r,
    ull acc[3][2], int rg, int rbase, int lane, int cbase,
    const float* __restrict__ lsrc, int lstr, const float* __restrict__ rsrc, int rstr)
{
    #pragma unroll 4
    for (int k = 0; k < 48; k++) {
        float2 v = *(const float2*)&hsh[k*128 + cbase];
        ull b0 = pack2(v.x,v.x), b1 = pack2(v.y,v.y);
        ull n0, n1;
        if (SHIFT < 0) {
            float pv = __shfl_up_sync(0xffffffffu, v.y, 1);
            if (lane == 0) pv = lsrc[k*lstr];
            n0 = pack2(pv,pv); n1 = b0;
        } else {
            float qv = __shfl_down_sync(0xffffffffu, v.x, 1);
            if (lane == 31) qv = rsrc[k*rstr];
            n0 = b1; n1 = pack2(qv,qv);
        }
        const ulonglong2* wrow = (const ulonglong2*)&sm[WEo_ + (k*24 + 3*rg)*4];
        #pragma unroll
        for (int p = 0; p < 3; p++) {
            ulonglong2 wv = wrow[p];
            acc[p][0] = fma2(wv.x, b0, acc[p][0]);
            acc[p][1] = fma2(wv.x, b1, acc[p][1]);
            acc[p][0] = fma2(wv.y, n0, acc[p][0]);
            acc[p][1] = fma2(wv.y, n1, acc[p][1]);
        }
    }
    #pragma unroll
    for (int kp = 0; kp < 4; kp++) {
        float2 ma = *(const float2*)&msg[(2*kp)*128 + cbase];
        float2 mb = *(const float2*)&msg[(2*kp+1)*128 + cbase];
        ull a0 = pack2(ma.x,ma.x), a1 = pack2(ma.y,ma.y);
        ull c0 = pack2(mb.x,mb.x), c1 = pack2(mb.y,mb.y);
        const ulonglong2* wq = (const ulonglong2*)&sm[WMo_ + (kp*24 + 3*rg)*4];
        #pragma unroll
        for (int p = 0; p < 3; p++) {
            ulonglong2 wv = wq[p];
            acc[p][0] = fma2(wv.x,a0,acc[p][0]);
            acc[p][1] = fma2(wv.x,a1,acc[p][1]);
            acc[p][0] = fma2(wv.y,c0,acc[p][0]);
            acc[p][1] = fma2(wv.y,c1,acc[p][1]);
        }
    }
    #pragma unroll
    for (int p = 0; p < 3; p++) {
        float x0,x1,y0,y1;
        unpack2(acc[p][0],x0,y0); unpack2(acc[p][1],x1,y1);
        int o0 = rbase + 2*p;
        *(float2*)&r[o0*128 + cbase]     = make_float2(fmaxf(x0,0.f), fmaxf(x1,0.f));
        *(float2*)&r[(o0+1)*128 + cbase] = make_float2(fmaxf(y0,0.f), fmaxf(y1,0.f));
    }
}

// edge y: center-only, k-pair quads
__device__ __forceinline__ void edge1y(const float* __restrict__ sm,
    const float* __restrict__ msg, const float* __restrict__ hsh, float* __restrict__ r,
    ull acc[3][2], int rg, int rbase, int cbase)
{
    #pragma unroll 2
    for (int kp = 0; kp < 24; kp++) {
        float2 va = *(const float2*)&hsh[(2*kp)*128 + cbase];
        float2 vb = *(const float2*)&hsh[(2*kp+1)*128 + cbase];
        ull a0 = pack2(va.x,va.x), a1 = pack2(va.y,va.y);
        ull c0 = pack2(vb.x,vb.x), c1 = pack2(vb.y,vb.y);
        const ulonglong2* wq = (const ulonglong2*)&sm[WYH + (kp*24 + 3*rg)*4];
        #pragma unroll
        for (int p = 0; p < 3; p++) {
            ulonglong2 wv = wq[p];
            acc[p][0] = fma2(wv.x,a0,acc[p][0]);
            acc[p][1] = fma2(wv.x,a1,acc[p][1]);
            acc[p][0] = fma2(wv.y,c0,acc[p][0]);
            acc[p][1] = fma2(wv.y,c1,acc[p][1]);
        }
    }
    #pragma unroll
    for (int kp = 0; kp < 4; kp++) {
        float2 ma = *(const float2*)&msg[(2*kp)*128 + cbase];
        float2 mb = *(const float2*)&msg[(2*kp+1)*128 + cbase];
        ull a0 = pack2(ma.x,ma.x), a1 = pack2(ma.y,ma.y);
        ull c0 = pack2(mb.x,mb.x), c1 = pack2(mb.y,mb.y);
        const ulonglong2* wq = (const ulonglong2*)&sm[WYM + (kp*24 + 3*rg)*4];
        #pragma unroll
        for (int p = 0; p < 3; p++) {
            ulonglong2 wv = wq[p];
            acc[p][0] = fma2(wv.x,a0,acc[p][0]);
            acc[p][1] = fma2(wv.x,a1,acc[p][1]);
            acc[p][0] = fma2(wv.y,c0,acc[p][0]);
            acc[p][1] = fma2(wv.y,c1,acc[p][1]);
        }
    }
    #pragma unroll
    for (int p = 0; p < 3; p++) {
        float x0,x1,y0,y1;
        unpack2(acc[p][0],x0,y0); unpack2(acc[p][1],x1,y1);
        int o0 = rbase + 2*p;
        *(float2*)&r[o0*128 + cbase]     = make_float2(fmaxf(x0,0.f), fmaxf(x1,0.f));
        *(float2*)&r[(o0+1)*128 + cbase] = make_float2(fmaxf(y0,0.f), fmaxf(y1,0.f));
    }
}

// layer2: k-pair quads
__device__ __forceinline__ void layer2v(const float* __restrict__ sm, int W2o_,
    const float* __restrict__ r, ull agg[3][2], int rg, int cbase)
{
    #pragma unroll 2
    for (int kp = 0; kp < 24; kp++) {
        float2 va = *(const float2*)&r[(2*kp)*128 + cbase];
        float2 vb = *(const float2*)&r[(2*kp+1)*128 + cbase];
        ull a0 = pack2(va.x,va.x), a1 = pack2(va.y,va.y);
        ull c0 = pack2(vb.x,vb.x), c1 = pack2(vb.y,vb.y);
        const ulonglong2* wq = (const ulonglong2*)&sm[W2o_ + (kp*24 + 3*rg)*4];
        #pragma unroll
        for (int p = 0; p < 3; p++) {
            ulonglong2 wv = wq[p];
            agg[p][0] = fma2(wv.x,a0,agg[p][0]);
            agg[p][1] = fma2(wv.x,a1,agg[p][1]);
            agg[p][0] = fma2(wv.y,c0,agg[p][0]);
            agg[p][1] = fma2(wv.y,c1,agg[p][1]);
        }
    }
}

__global__ void __launch_bounds__(TPB, 1)
persist_kernel(const float* __restrict__ ys, const float* __restrict__ hx0,
            const float* __restrict__ Fm, const float* __restrict__ Hm,
            const float* __restrict__ Qm, const float* __restrict__ Rm,
            const float* __restrict__ W_hy, const float* __restrict__ b_hy,
            float* __restrict__ out, int iters,
            const float* __restrict__ W1p, const float* __restrict__ b1p,
            const float* __restrict__ W2p, const float* __restrict__ b2p,
            const float* __restrict__ W1f, const float* __restrict__ b1f,
            const float* __restrict__ W2f, const float* __restrict__ b2f,
            const float* __restrict__ W1y, const float* __restrict__ b1y,
            const float* __restrict__ W2y, const float* __restrict__ b2y,
            const float* __restrict__ Wih, const float* __restrict__ bih,
            const float* __restrict__ Whh, const float* __restrict__ bhh,
            const float* __restrict__ Wdec, const float* __restrict__ bdec) {
    extern __shared__ float sm[];
    float* xsh = sm + XSH;
    float* buf0 = sm + BUF0;  float* buf1 = sm + BUF1;  float* scr = sm + SCR;

    const int tid = threadIdx.x;
    const int b = blockIdx.y;
    const int c = blockIdx.x;
    const int t0 = c * NT;

    // ================= INIT =================
    {   // fp64 GJ in scr overlay
        double* dA8 = (double*)scr;
        double* dI8 = dA8 + 64;
        double* dA4 = dI8 + 64;
        double* dI4 = dA4 + 16;
        double* dT2 = dI4 + 16;
        double* dTH = dT2 + 64;
        const int r8 = tid >> 3, j8 = tid & 7;
        if (tid < 64) {
            dA8[tid] = (double)Qm[tid]; dI8[tid] = (r8==j8) ? 1.0 : 0.0;
            if (tid < 16) { dA4[tid] = (double)Rm[tid]; dI4[tid] = ((tid>>2)==(tid&3)) ? 1.0 : 0.0; }
        }
        __syncthreads();
        for (int cg2 = 0; cg2 < 8; cg2++) {
            double piv=1.0, f=0.0, acj=0.0, icj=0.0;
            if (tid < 64) {
                piv = dA8[cg2*8+cg2]; f = dA8[r8*8+cg2]/piv;
                acj = dA8[cg2*8+j8]; icj = dI8[cg2*8+j8];
            }
            __syncthreads();
            if (tid < 64) {
                if (r8 == cg2) { dA8[tid] = acj/piv; dI8[tid] = icj/piv; }
                else           { dA8[tid] -= f*acj;  dI8[tid] -= f*icj; }
            }
            __syncthreads();
        }
        for (int cg2 = 0; cg2 < 4; cg2++) {
            double piv=1.0, f=0.0, acj=0.0, icj=0.0;
            if (tid < 16) {
                int r4 = tid>>2;
                piv = dA4[cg2*4+cg2]; f = dA4[r4*4+cg2]/piv;
                acj = dA4[cg2*4+(tid&3)]; icj = dI4[cg2*4+(tid&3)];
            }
            __syncthreads();
            if (tid < 16) {
                int r4 = tid>>2;
                if (r4 == cg2) { dA4[tid] = acj/piv; dI4[tid] = icj/piv; }
                else           { dA4[tid] -= f*acj;  dI4[tid] -= f*icj; }
            }
            __syncthreads();
        }
        if (tid < 64) {
            sm[SQI+tid] = (float)dI8[tid];
            double s = 0;
            for (int k = 0; k < 8; k++) s += dI8[r8*8+k]*(double)Fm[k*8+j8];
            sm[SQIF+tid] = (float)s;
            s = 0;
            for (int k = 0; k < 8; k++) s += (double)Fm[k*8+r8]*dI8[k*8+j8];
            dT2[tid] = s; sm[SFTQI+tid] = (float)s;
            if (tid < 32) {
                int i = tid>>2, z = tid&3;
                double u = 0;
                for (int y = 0; y < 4; y++) u += (double)Hm[y*8+i]*dI4[y*4+z];
                dTH[tid] = u; sm[MPo+tid] = (float)u;   // HtRi parked
            }
        }
        __syncthreads();
        if (tid < 64) {
            double s = 0;
            for (int k = 0; k < 8; k++) s += dT2[r8*8+k]*(double)Fm[k*8+j8];
            sm[SFTQIF+tid] = (float)s;
            s = 0;
            for (int z = 0; z < 4; z++) s += dTH[r8*4+z]*(double)Hm[z*8+j8];
            sm[SHTRIH+tid] = (float)s;
        }
        if (tid < 48) sm[B2S+tid] = b2p[tid]+b2f[tid]+b2y[tid];
        __syncthreads();
    }

    // weights staged once
    for (int idx = tid; idx < 48*24; idx += TPB) {
        int k = idx/24, p = idx - k*24;
        float* d = &sm[WEP + idx*4];
        d[0] = W1p[(2*p)*104 + k];      d[1] = W1p[(2*p+1)*104 + k];
        d[2] = W1p[(2*p)*104 + 48 + k]; d[3] = W1p[(2*p+1)*104 + 48 + k];
        float* e = &sm[WEF + idx*4];
        e[0] = W1f[(2*p)*104 + k];      e[1] = W1f[(2*p+1)*104 + k];
        e[2] = W1f[(2*p)*104 + 48 + k]; e[3] = W1f[(2*p+1)*104 + 48 + k];
    }
    // k-pair quads: [kp][op]{w(k,o0),w(k,o1),w(k+1,o0),w(k+1,o1)}
    for (int idx = tid; idx < 48*48; idx += TPB) {
        int o = idx/48, k = idx - o*48;
        int d = ((k>>1)*24 + (o>>1))*4 + (k&1)*2 + (o&1);
        sm[WYH + d] = W1y[o*104 + k];
        sm[W2P + d] = W2p[idx];
        sm[W2F + d] = W2f[idx];
        sm[W2Y + d] = W2y[idx];
    }
    for (int idx = tid; idx < 48*72; idx += TPB) {
        int k = idx/72, p = idx - k*72;
        float* d = &sm[WG + idx*4];
        d[0] = Wih[(2*p)*48 + k]; d[1] = Wih[(2*p+1)*48 + k];
        d[2] = Whh[(2*p)*48 + k]; d[3] = Whh[(2*p+1)*48 + k];
    }
    for (int idx = tid; idx < 48*8; idx += TPB) {
        int o = idx/8, k = idx - o*8;
        int d = ((k>>1)*24 + (o>>1))*4 + (k&1)*2 + (o&1);
        sm[WPM + d] = W1p[o*104 + 96 + k];
        sm[WFM + d] = W1f[o*104 + 96 + k];
        sm[WYM + d] = W1y[o*104 + 96 + k];
    }
    for (int idx = tid; idx < 384; idx += TPB) sm[WDEC+idx]=Wdec[idx];
    if (tid < 48) { sm[B1P+tid]=b1p[tid]; sm[B1F+tid]=b1f[tid]; }
    for (int idx = tid; idx < 144; idx += TPB) { sm[BIH+idx]=bih[idx]; sm[BHH+idx]=bhh[idx]; }
    if (tid < 8) sm[BDEC+tid]=bdec[tid];

    // state init: hsh, halos, xsh = H^T y, hy -> buf1 (temp)
    for (int idx = tid; idx < 48*128; idx += TPB) {
        int k = idx >> 7, cc = idx & 127; int t = t0 + cc;
        buf0[idx] = (t < Tn) ? hx0[(b*48+k)*Tn + t] : 0.f;
    }
    if (tid < 48) {
        int tl = t0 - 1, tr = t0 + 128;
        sm[HLo+tid] = (tl >= 0) ? hx0[(b*48+tid)*Tn + tl] : 0.f;
        sm[HRo+tid] = (tr < Tn) ? hx0[(b*48+tid)*Tn + tr] : 0.f;
    }
    for (int idx = tid; idx < 8*130; idx += TPB) {
        int k = idx / 130, cc = idx - k*130; int t = t0 + cc - 1;
        float v = 0.f;
        if (t >= 0 && t < Tn) {
            const float* yp = &ys[((size_t)b*Tn + t)*4];
            #pragma unroll
            for (int y = 0; y < 4; y++) v = fmaf(Hm[y*8+k], yp[y], v);
        }
        xsh[idx] = v;
    }
    for (int idx = tid; idx < 48*128; idx += TPB) {
        int o = idx >> 7, cc = idx & 127; int t = t0 + cc;
        float s = 0.f;
        if (t < Tn) {
            const float* yp = &ys[((size_t)b*Tn + t)*4];
            s = b_hy[o];
            #pragma unroll
            for (int y = 0; y < 4; y++) s = fmaf(W_hy[o*4+y], yp[y], s);
        }
        buf1[idx] = s;   // hy (temp)
    }
    __syncthreads();

    const int w = tid >> 5, lane = tid & 31, cg = w & 1, rg = w >> 1;
    const int rbase = 6*rg, cbase = cg*64 + 2*lane;
    const int inv = Tn - t0;

    // per-thread cy registers (HtRi parked at MPo)
    float cy0 = 0.f, cy1 = 0.f;
    {
        int i0 = tid >> 7, n0 = tid & 127, ta = t0 + n0;
        if (ta < Tn) {
            const float* yp = &ys[((size_t)b*Tn + ta)*4];
            #pragma unroll
            for (int y = 0; y < 4; y++) cy0 = fmaf(sm[MPo+i0*4+y], yp[y], cy0);
        }
        int i1 = (tid+TPB) >> 7, n1 = (tid+TPB) & 127, tb = t0 + n1;
        if (tb < Tn) {
            const float* yp = &ys[((size_t)b*Tn + tb)*4];
            #pragma unroll
            for (int y = 0; y < 4; y++) cy1 = fmaf(sm[MPo+i1*4+y], yp[y], cy1);
        }
    }

    // yterm registers from hy (in buf1)
    ull ytr0[3], ytr1[3];
    #pragma unroll
    for (int p = 0; p < 3; p++) {
        int o0 = rbase + 2*p, o1 = o0 + 1;
        float a0=0.f, a1=0.f, b0v=0.f, b1v=0.f;
        if (t0 + cbase < Tn) {
            a0 = b1y[o0]; a1 = b1y[o1];
            for (int k = 0; k < 48; k++) {
                float hv = buf1[k*128 + cbase];
                a0 = fmaf(W1y[o0*104+48+k], hv, a0);
                a1 = fmaf(W1y[o1*104+48+k], hv, a1);
            }
        }
        if (t0 + cbase + 1 < Tn) {
            b0v = b1y[o0]; b1v = b1y[o1];
            for (int k = 0; k < 48; k++) {
                float hv = buf1[k*128 + cbase + 1];
                b0v = fmaf(W1y[o0*104+48+k], hv, b0v);
                b1v = fmaf(W1y[o1*104+48+k], hv, b1v);
            }
        }
        ytr0[p] = pack2(a0, a1);
        ytr1[p] = pack2(b0v, b1v);
    }
    __syncthreads();

    // prologue messages (it=0, halos fresh)
    msgphase(sm, xsh, t0, tid, cy0, cy1);
    __syncthreads();

    // ================= MAIN LOOP (R12 structure) =================
    for (int it = 0; it < iters; it++) {
        float* hcur  = (it & 1) ? buf1 : buf0;
        float* hnext = (it & 1) ? buf0 : buf1;
        const float* lsrc; int lstr; const float* rsrc; int rstr;
        if (cg == 0) { lsrc = sm+HLo; lstr = 1; rsrc = hcur+64; rstr = 128; }
        else         { lsrc = hcur+63; lstr = 128; rsrc = sm+HRo; rstr = 1; }

        ull agg[3][2];
        #pragma unroll
        for (int p = 0; p < 3; p++) {
            ull bp = *(const ull*)&sm[B2S + rbase + 2*p];
            agg[p][0] = bp; agg[p][1] = bp;
        }
        // B: edge_p -> hnext
        {
            ull acc[3][2];
            #pragma unroll
            for (int p = 0; p < 3; p++) { ull bp = *(const ull*)&sm[B1P+rbase+2*p]; acc[p][0]=bp; acc[p][1]=bp; }
            edge1pf<-1>(sm, WEP, WPM, sm+MPo, hcur, hnext, acc, rg, rbase, lane, cbase, lsrc, lstr, rsrc, rstr);
        }
        __syncthreads();
        // C: layer2p(hnext) ; edge_f -> scr
        layer2v(sm, W2P, hnext, agg, rg, cbase);
        {
            ull acc[3][2];
            #pragma unroll
            for (int p = 0; p < 3; p++) { ull bp = *(const ull*)&sm[B1F+rbase+2*p]; acc[p][0]=bp; acc[p][1]=bp; }
            edge1pf<1>(sm, WEF, WFM, sm+MFo, hcur, scr, acc, rg, rbase, lane, cbase, lsrc, lstr, rsrc, rstr);
        }
        __syncthreads();
        // D: layer2f(scr) ; edge_y -> hnext
        layer2v(sm, W2F, scr, agg, rg, cbase);
        {
            ull acc[3][2];
            #pragma unroll
            for (int p = 0; p < 3; p++) { acc[p][0] = ytr0[p]; acc[p][1] = ytr1[p]; }
            edge1y(sm, sm+MYo, hcur, hnext, acc, rg, rbase, cbase);
        }
        __syncthreads();
        // E: layer2y(hnext) ; spill agg -> scr
        layer2v(sm, W2Y, hnext, agg, rg, cbase);
        #pragma unroll
        for (int p = 0; p < 3; p++) {
            float x0,x1,y0,y1;
            unpack2(agg[p][0],x0,y0); unpack2(agg[p][1],x1,y1);
            int o0 = rbase + 2*p;
            *(float2*)&scr[o0*128+cbase]     = make_float2(x0, x1);
            *(float2*)&scr[(o0+1)*128+cbase] = make_float2(y0, y1);
        }
        __syncthreads();

        // F: GRU
        {
            ull A[9][2], Bv[3][2];
            #pragma unroll
            for (int g = 0; g < 3; g++)
                #pragma unroll
                for (int p = 0; p < 3; p++) {
                    ull bi = *(const ull*)&sm[BIH + g*48 + rbase + 2*p];
                    if (g < 2) bi = add2(bi, *(const ull*)&sm[BHH + g*48 + rbase + 2*p]);
                    A[g*3+p][0] = bi; A[g*3+p][1] = bi;
                }
            #pragma unroll
            for (int p = 0; p < 3; p++) {
                ull bb = *(const ull*)&sm[BHH + 96 + rbase + 2*p];
                Bv[p][0] = bb; Bv[p][1] = bb;
            }
            #pragma unroll 2
            for (int k = 0; k < 48; k++) {
                float2 xv = *(const float2*)&scr[k*128 + cbase];
                float2 hv = *(const float2*)&hcur[k*128 + cbase];
                ull xb0 = pack2(xv.x,xv.x), xb1 = pack2(xv.y,xv.y);
                ull hb0 = pack2(hv.x,hv.x), hb1 = pack2(hv.y,hv.y);
                const ulonglong2* wg = (const ulonglong2*)&sm[WG + k*72*4];
                #pragma unroll
                for (int j = 0; j < 3; j++) {
                    ulonglong2 w0 = wg[3*rg + j];
                    A[j][0] = fma2(w0.x, xb0, A[j][0]); A[j][1] = fma2(w0.x, xb1, A[j][1]);
                    A[j][0] = fma2(w0.y, hb0, A[j][0]); A[j][1] = fma2(w0.y, hb1, A[j][1]);
                    ulonglong2 w1 = wg[24 + 3*rg + j];
                    A[3+j][0] = fma2(w1.x, xb0, A[3+j][0]); A[3+j][1] = fma2(w1.x, xb1, A[3+j][1]);
                    A[3+j][0] = fma2(w1.y, hb0, A[3+j][0]); A[3+j][1] = fma2(w1.y, hb1, A[3+j][1]);
                    ulonglong2 w2 = wg[48 + 3*rg + j];
                    A[6+j][0] = fma2(w2.x, xb0, A[6+j][0]); A[6+j][1] = fma2(w2.x, xb1, A[6+j][1]);
                    Bv[j][0]  = fma2(w2.y, hb0, Bv[j][0]);  Bv[j][1]  = fma2(w2.y, hb1, Bv[j][1]);
                }
            }
            #pragma unroll
            for (int p = 0; p < 3; p++) {
                float rA0,rB0,rA1,rB1, zA0,zB0,zA1,zB1, nA0,nB0,nA1,nB1, bA0,bB0,bA1,bB1;
                unpack2(A[p][0],rA0,rB0);   unpack2(A[p][1],rA1,rB1);
                unpack2(A[3+p][0],zA0,zB0); unpack2(A[3+p][1],zA1,zB1);
                unpack2(A[6+p][0],nA0,nB0); unpack2(A[6+p][1],nA1,nB1);
                unpack2(Bv[p][0],bA0,bB0);  unpack2(Bv[p][1],bA1,bB1);
                int o0 = rbase + 2*p, o1 = o0 + 1;
                float2 h0 = *(const float2*)&hcur[o0*128 + cbase];
                float2 h1 = *(const float2*)&hcur[o1*128 + cbase];
                float v00, v01, v10, v11;
                { float rr=sigmf(rA0), zz=sigmf(zA0), ng=tanhfast(nA0+rr*bA0); v00=(1.f-zz)*ng+zz*h0.x; }
                { float rr=sigmf(rA1), zz=sigmf(zA1), ng=tanhfast(nA1+rr*bA1); v01=(1.f-zz)*ng+zz*h0.y; }
                { float rr=sigmf(rB0), zz=sigmf(zB0), ng=tanhfast(nB0+rr*bB0); v10=(1.f-zz)*ng+zz*h1.x; }
                { float rr=sigmf(rB1), zz=sigmf(zB1), ng=tanhfast(nB1+rr*bB1); v11=(1.f-zz)*ng+zz*h1.y; }
                *(float2*)&hnext[o0*128+cbase] = make_float2(v00, v01);
                *(float2*)&hnext[o1*128+cbase] = make_float2(v10, v11);
            }
        }
        __syncthreads();

        // G: shift-leak guard, publish, decoder
        const int par = it & 1;
        if (inv < 128 && tid < 48) hnext[tid*128 + inv] = 0.f;
        if (tid < 48) {
            g_hh[par][b][c][0][tid] = hnext[tid*128 + 0];
            int t127 = t0 + 127;
            g_hh[par][b][c][1][tid] = (t127 < Tn) ? hnext[tid*128 + 127] : 0.f;
        }
        {
            float* outp = out + (size_t)BXT * (1 + it);
            bool last = (it == iters - 1);
            #pragma unroll
            for (int rep = 0; rep < 2; rep++) {
                int item = tid + rep*TPB;
                int i = item >> 7, n = item & 127, t = t0 + n;
                float e = sm[BDEC+i];
                #pragma unroll 8
                for (int k = 0; k < 48; k++) e = fmaf(sm[WDEC+i*48+k], hnext[k*128+n], e);
                float xn = 0.f;
                if (t < Tn) {
                    xn = xsh[i*130 + 1 + n]
                       + GAMMA_F * (e + sm[MPo+i*128+n] + sm[MFo+i*128+n] + sm[MYo+i*128+n]);
                    xsh[i*130 + 1 + n] = xn;
                    outp[(b*8+i)*Tn + t] = xn;
                    if (last) out[(b*8+i)*Tn + t] = xn;
                }
                if (n == 0)   g_xh[par][b][c][0][i] = xn;
                if (n == 127) g_xh[par][b][c][1][i] = xn;
            }
        }
        __syncthreads();

        if (it + 1 < iters) {
            unsigned gen = 0;
            if (tid == 0) {
                gen = g_gen;
                __threadfence();
                if (atomicAdd(&g_cnt, 1u) == NBLK-1u) {
                    g_cnt = 0;
                    __threadfence();
                    g_gen = gen + 1u;
                }
            }
            msgphase(sm, xsh, t0, tid, cy0, cy1);   // boundary cols provisional
            if (tid == 0) {
                while (g_gen == gen) { __nanosleep(32); }
                __threadfence();
            }
            __syncthreads();
            if (tid < 48) {
                sm[HLo+tid] = (c > 0) ? g_hh[par][b][c-1][1][tid] : 0.f;
            } else if (tid < 96) {
                int k = tid-48;
                sm[HRo+k] = (c < NCHUNK-1) ? g_hh[par][b][c+1][0][k] : 0.f;
            } else if (tid < 104) {
                int i = tid-96;
                float a = 0.f;
                if (c > 0) {
                    const float* xl = g_xh[par][b][c-1][1];
                    #pragma unroll
                    for (int j = 0; j < 8; j++)
                        a += -sm[SQI+i*8+j]*xsh[j*130+1] + sm[SQIF+i*8+j]*xl[j];
                }
                sm[MPo + i*128 + 0] = a;
            } else if (tid < 112) {
                int i = tid-104;
                float a = 0.f;
                if (c < NCHUNK-1) {
                    const float* xr = g_xh[par][b][c+1][0];
                    #pragma unroll
                    for (int j = 0; j < 8; j++)
                        a += sm[SFTQI+i*8+j]*xr[j] - sm[SFTQIF+i*8+j]*xsh[j*130+128];
                }
                sm[MFo + i*128 + 127] = a;
            }
            __syncthreads();
        }
    }
}

extern "C" void kernel_launch(void* const* d_in, const int* in_sizes, int n_in,
                              void* d_out, int out_size) {
    const float* ys   = (const float*)d_in[0];
    const float* hx0  = (const float*)d_in[1];
    const float* F    = (const float*)d_in[2];
    const float* H    = (const float*)d_in[3];
    const float* Q    = (const float*)d_in[4];
    const float* R    = (const float*)d_in[5];
    const float* W_hy = (const float*)d_in[6];
    const float* b_hy = (const float*)d_in[7];
    const float* W1p  = (const float*)d_in[8];
    const float* b1p  = (const float*)d_in[9];
    const float* W2p  = (const float*)d_in[10];
    const float* b2p  = (const float*)d_in[11];
    const float* W1f  = (const float*)d_in[12];
    const float* b1f  = (const float*)d_in[13];
    const float* W2f  = (const float*)d_in[14];
    const float* b2f  = (const float*)d_in[15];
    const float* W1y  = (const float*)d_in[16];
    const float* b1y  = (const float*)d_in[17];
    const float* W2y  = (const float*)d_in[18];
    const float* b2y  = (const float*)d_in[19];
    const float* Wih  = (const float*)d_in[20];
    const float* bih  = (const float*)d_in[21];
    const float* Whh  = (const float*)d_in[22];
    const float* bhh  = (const float*)d_in[23];
    const float* Wdec = (const float*)d_in[24];
    const float* bdec = (const float*)d_in[25];
    float* out = (float*)d_out;

    const int iters = out_size / BXT - 1;

    cudaFuncSetAttribute(persist_kernel, cudaFuncAttributeMaxDynamicSharedMemorySize, SMEM_BYTES);

    dim3 grid(NCHUNK, Bn);
    persist_kernel<<<grid, TPB, SMEM_BYTES>>>(ys, hx0, F, H, Q, R, W_hy, b_hy,
        out, iters,
        W1p, b1p, W2p, b2p, W1f, b1f, W2f, b2f, W1y, b1y, W2y, b2y,
        Wih, bih, Whh, bhh, Wdec, bdec);
}

// round 17
// speedup vs baseline: 1.0487x; 1.0487x over previous
#include <cuda_runtime.h>
#include <math.h>
typedef unsigned long long ull;

#define Bn 16
#define Tn 1000
#define NT 128
#define TPB 512
#define NCHUNK 8
#define NBLK (Bn*NCHUNK)
#define GAMMA_F 1e-4f
#define BXT (Bn*8*Tn)

__device__ float g_hh[2][Bn][NCHUNK][2][48];
__device__ float g_xh[2][Bn][NCHUNK][2][8];
__device__ volatile unsigned g_flag[Bn][NCHUNK*32];   // padded: one 128B line per flag

// shared layout (floats)
constexpr int WEP=0, WEF=4608, WYH=9216;
constexpr int W2P=11520, W2F=13824, W2Y=16128;
constexpr int WG=18432;
constexpr int WPM=32256, WFM=32640, WYM=33024, WDEC=33408;
constexpr int B1P=33792, B1F=33840, B2S=33888, BIH=33936, BHH=34080, BDEC=34224;
constexpr int SQI=34232, SQIF=34296, SFTQI=34360, SFTQIF=34424, SHTRIH=34488;
constexpr int HLo=34552, HRo=34600;
constexpr int BUF0=34648;           // 48x128
constexpr int XSH=40792;            // 8x130 halo
constexpr int MPo=41832, MFo=42856, MYo=43880;
constexpr int BUF1=44904, SCR=51048; // 48x128 each
constexpr int SMEM_FLOATS=57192;
constexpr int SMEM_BYTES=SMEM_FLOATS*4;  // 228,768 B

__device__ __forceinline__ ull pack2(float a, float b){ull r;asm("mov.b64 %0,{%1,%2};":"=l"(r):"f"(a),"f"(b));return r;}
__device__ __forceinline__ void unpack2(ull v, float&a, float&b){asm("mov.b64 {%0,%1},%2;":"=f"(a),"=f"(b):"l"(v));}
__device__ __forceinline__ ull fma2(ull a, ull b, ull c){ull d;asm("fma.rn.f32x2 %0,%1,%2,%3;":"=l"(d):"l"(a),"l"(b),"l"(c));return d;}
__device__ __forceinline__ ull add2(ull a, ull b){ull d;asm("add.rn.f32x2 %0,%1,%2;":"=l"(d):"l"(a),"l"(b));return d;}
__device__ __forceinline__ float sigmf(float x){ return 1.f/(1.f+__expf(-x)); }
__device__ __forceinline__ float tanhfast(float x){ return 1.f - 2.f/(__expf(2.f*x)+1.f); }

__device__ __forceinline__ void msgphase(float* __restrict__ sm, float* __restrict__ xsh,
                                         int t0, int tid, float cy0, float cy1) {
    #pragma unroll
    for (int rep = 0; rep < 2; rep++) {
        int item = tid + rep*TPB;
        int i = item >> 7, n = item & 127, t = t0 + n;
        bool valid = t < Tn;
        float accp = 0.f, accf = 0.f;
        float accy = (rep == 0) ? cy0 : cy1;
        #pragma unroll
        for (int j = 0; j < 8; j++) {
            float xc = xsh[j*130 + 1 + n];
            accp = fmaf(-sm[SQI+i*8+j], xc, accp);
            accp = fmaf(sm[SQIF+i*8+j], xsh[j*130 + n], accp);
            accf = fmaf(sm[SFTQI+i*8+j], xsh[j*130 + 2 + n], accf);
            accf = fmaf(-sm[SFTQIF+i*8+j], xc, accf);
            accy = fmaf(-sm[SHTRIH+i*8+j], xc, accy);
        }
        sm[MPo + i*128+n] = (valid && t > 0) ? accp : 0.f;
        sm[MFo + i*128+n] = (t < Tn-1) ? accf : 0.f;
        sm[MYo + i*128+n] = valid ? accy : 0.f;
    }
}

// edge (past/fut): interleaved center+neighbor weight quads
template<int SHIFT>
__device__ __forceinline__ void edge1pf(const float* __restrict__ sm, int WEo_, int WMo_,
    const float* __restrict__ msg, const float* __restrict__ hsh, float* __restrict__ r,
    ull acc[3][2], int rg, int rbase, int lane, int cbase,
    const float* __restrict__ lsrc, int lstr, const float* __restrict__ rsrc, int rstr)
{
    #pragma unroll 4
    for (int k = 0; k < 48; k++) {
        float2 v = *(const float2*)&hsh[k*128 + cbase];
        ull b0 = pack2(v.x,v.x), b1 = pack2(v.y,v.y);
        ull n0, n1;
        if (SHIFT < 0) {
            float pv = __shfl_up_sync(0xffffffffu, v.y, 1);
            if (lane == 0) pv = lsrc[k*lstr];
            n0 = pack2(pv,pv); n1 = b0;
        } else {
            float qv = __shfl_down_sync(0xffffffffu, v.x, 1);
            if (lane == 31) qv = rsrc[k*rstr];
            n0 = b1; n1 = pack2(qv,qv);
        }
        const ulonglong2* wrow = (const ulonglong2*)&sm[WEo_ + (k*24 + 3*rg)*4];
        #pragma unroll
        for (int p = 0; p < 3; p++) {
            ulonglong2 wv = wrow[p];
            acc[p][0] = fma2(wv.x, b0, acc[p][0]);
            acc[p][1] = fma2(wv.x, b1, acc[p][1]);
            acc[p][0] = fma2(wv.y, n0, acc[p][0]);
            acc[p][1] = fma2(wv.y, n1, acc[p][1]);
        }
    }
    #pragma unroll
    for (int k = 0; k < 8; k++) {
        float2 m = *(const float2*)&msg[k*128 + cbase];
        ull b0 = pack2(m.x,m.x), b1 = pack2(m.y,m.y);
        #pragma unroll
        for (int p = 0; p < 3; p++) {
            ull wp = *(const ull*)&sm[WMo_ + k*48 + rbase + 2*p];
            acc[p][0] = fma2(wp,b0,acc[p][0]);
            acc[p][1] = fma2(wp,b1,acc[p][1]);
        }
    }
    #pragma unroll
    for (int p = 0; p < 3; p++) {
        float x0,x1,y0,y1;
        unpack2(acc[p][0],x0,y0); unpack2(acc[p][1],x1,y1);
        int o0 = rbase + 2*p;
        r[o0*128 + cbase]       = fmaxf(x0,0.f);
        r[o0*128 + cbase+1]     = fmaxf(x1,0.f);
        r[(o0+1)*128 + cbase]   = fmaxf(y0,0.f);
        r[(o0+1)*128 + cbase+1] = fmaxf(y1,0.f);
    }
}

// edge y: center-only
__device__ __forceinline__ void edge1y(const float* __restrict__ sm,
    const float* __restrict__ msg, const float* __restrict__ hsh, float* __restrict__ r,
    ull acc[3][2], int rbase, int cbase)
{
    #pragma unroll 4
    for (int k = 0; k < 48; k++) {
        float2 v = *(const float2*)&hsh[k*128 + cbase];
        ull b0 = pack2(v.x,v.x), b1 = pack2(v.y,v.y);
        #pragma unroll
        for (int p = 0; p < 3; p++) {
            ull wp = *(const ull*)&sm[WYH + k*48 + rbase + 2*p];
            acc[p][0] = fma2(wp,b0,acc[p][0]);
            acc[p][1] = fma2(wp,b1,acc[p][1]);
        }
    }
    #pragma unroll
    for (int k = 0; k < 8; k++) {
        float2 m = *(const float2*)&msg[k*128 + cbase];
        ull b0 = pack2(m.x,m.x), b1 = pack2(m.y,m.y);
        #pragma unroll
        for (int p = 0; p < 3; p++) {
            ull wp = *(const ull*)&sm[WYM + k*48 + rbase + 2*p];
            acc[p][0] = fma2(wp,b0,acc[p][0]);
            acc[p][1] = fma2(wp,b1,acc[p][1]);
        }
    }
    #pragma unroll
    for (int p = 0; p < 3; p++) {
        float x0,x1,y0,y1;
        unpack2(acc[p][0],x0,y0); unpack2(acc[p][1],x1,y1);
        int o0 = rbase + 2*p;
        r[o0*128 + cbase]       = fmaxf(x0,0.f);
        r[o0*128 + cbase+1]     = fmaxf(x1,0.f);
        r[(o0+1)*128 + cbase]   = fmaxf(y0,0.f);
        r[(o0+1)*128 + cbase+1] = fmaxf(y1,0.f);
    }
}

__device__ __forceinline__ void layer2v(const float* __restrict__ sm, int W2o_,
    const float* __restrict__ r, ull agg[3][2], int rbase, int cbase)
{
    #pragma unroll 4
    for (int k = 0; k < 48; k++) {
        float2 v = *(const float2*)&r[k*128 + cbase];
        ull b0 = pack2(v.x,v.x), b1 = pack2(v.y,v.y);
        #pragma unroll
        for (int p = 0; p < 3; p++) {
            ull wp = *(const ull*)&sm[W2o_ + k*48 + rbase + 2*p];
            agg[p][0] = fma2(wp,b0,agg[p][0]);
            agg[p][1] = fma2(wp,b1,agg[p][1]);
        }
    }
}

__global__ void __launch_bounds__(TPB, 1)
persist_kernel(const float* __restrict__ ys, const float* __restrict__ hx0,
            const float* __restrict__ Fm, const float* __restrict__ Hm,
            const float* __restrict__ Qm, const float* __restrict__ Rm,
            const float* __restrict__ W_hy, const float* __restrict__ b_hy,
            float* __restrict__ out, int iters,
            const float* __restrict__ W1p, const float* __restrict__ b1p,
            const float* __restrict__ W2p, const float* __restrict__ b2p,
            const float* __restrict__ W1f, const float* __restrict__ b1f,
            const float* __restrict__ W2f, const float* __restrict__ b2f,
            const float* __restrict__ W1y, const float* __restrict__ b1y,
            const float* __restrict__ W2y, const float* __restrict__ b2y,
            const float* __restrict__ Wih, const float* __restrict__ bih,
            const float* __restrict__ Whh, const float* __restrict__ bhh,
            const float* __restrict__ Wdec, const float* __restrict__ bdec) {
    extern __shared__ float sm[];
    float* xsh = sm + XSH;
    float* buf0 = sm + BUF0;  float* buf1 = sm + BUF1;  float* scr = sm + SCR;

    const int tid = threadIdx.x;
    const int b = blockIdx.y;
    const int c = blockIdx.x;
    const int t0 = c * NT;

    // monotonic progress base (all flags equal at launch / replay)
    const unsigned base = g_flag[b][c*32];

    // ================= INIT =================
    {   // fp64 GJ in scr overlay
        double* dA8 = (double*)scr;
        double* dI8 = dA8 + 64;
        double* dA4 = dI8 + 64;
        double* dI4 = dA4 + 16;
        double* dT2 = dI4 + 16;
        double* dTH = dT2 + 64;
        const int r8 = tid >> 3, j8 = tid & 7;
        if (tid < 64) {
            dA8[tid] = (double)Qm[tid]; dI8[tid] = (r8==j8) ? 1.0 : 0.0;
            if (tid < 16) { dA4[tid] = (double)Rm[tid]; dI4[tid] = ((tid>>2)==(tid&3)) ? 1.0 : 0.0; }
        }
        __syncthreads();
        for (int cg2 = 0; cg2 < 8; cg2++) {
            double piv=1.0, f=0.0, acj=0.0, icj=0.0;
            if (tid < 64) {
                piv = dA8[cg2*8+cg2]; f = dA8[r8*8+cg2]/piv;
                acj = dA8[cg2*8+j8]; icj = dI8[cg2*8+j8];
            }
            __syncthreads();
            if (tid < 64) {
                if (r8 == cg2) { dA8[tid] = acj/piv; dI8[tid] = icj/piv; }
                else           { dA8[tid] -= f*acj;  dI8[tid] -= f*icj; }
            }
            __syncthreads();
        }
        for (int cg2 = 0; cg2 < 4; cg2++) {
            double piv=1.0, f=0.0, acj=0.0, icj=0.0;
            if (tid < 16) {
                int r4 = tid>>2;
                piv = dA4[cg2*4+cg2]; f = dA4[r4*4+cg2]/piv;
                acj = dA4[cg2*4+(tid&3)]; icj = dI4[cg2*4+(tid&3)];
            }
            __syncthreads();
            if (tid < 16) {
                int r4 = tid>>2;
                if (r4 == cg2) { dA4[tid] = acj/piv; dI4[tid] = icj/piv; }
                else           { dA4[tid] -= f*acj;  dI4[tid] -= f*icj; }
            }
            __syncthreads();
        }
        if (tid < 64) {
            sm[SQI+tid] = (float)dI8[tid];
            double s = 0;
            for (int k = 0; k < 8; k++) s += dI8[r8*8+k]*(double)Fm[k*8+j8];
            sm[SQIF+tid] = (float)s;
            s = 0;
            for (int k = 0; k < 8; k++) s += (double)Fm[k*8+r8]*dI8[k*8+j8];
            dT2[tid] = s; sm[SFTQI+tid] = (float)s;
            if (tid < 32) {
                int i = tid>>2, z = tid&3;
                double u = 0;
                for (int y = 0; y < 4; y++) u += (double)Hm[y*8+i]*dI4[y*4+z];
                dTH[tid] = u; sm[MPo+tid] = (float)u;   // HtRi parked
            }
        }
        __syncthreads();
        if (tid < 64) {
            double s = 0;
            for (int k = 0; k < 8; k++) s += dT2[r8*8+k]*(double)Fm[k*8+j8];
            sm[SFTQIF+tid] = (float)s;
            s = 0;
            for (int z = 0; z < 4; z++) s += dTH[r8*4+z]*(double)Hm[z*8+j8];
            sm[SHTRIH+tid] = (float)s;
        }
        if (tid < 48) sm[B2S+tid] = b2p[tid]+b2f[tid]+b2y[tid];
        __syncthreads();
    }

    // weights staged once
    for (int idx = tid; idx < 48*24; idx += TPB) {
        int k = idx/24, p = idx - k*24;
        float* d = &sm[WEP + idx*4];
        d[0] = W1p[(2*p)*104 + k];      d[1] = W1p[(2*p+1)*104 + k];
        d[2] = W1p[(2*p)*104 + 48 + k]; d[3] = W1p[(2*p+1)*104 + 48 + k];
        float* e = &sm[WEF + idx*4];
        e[0] = W1f[(2*p)*104 + k];      e[1] = W1f[(2*p+1)*104 + k];
        e[2] = W1f[(2*p)*104 + 48 + k]; e[3] = W1f[(2*p+1)*104 + 48 + k];
    }
    for (int idx = tid; idx < 48*48; idx += TPB) {
        int o = idx/48, k = idx - o*48;
        sm[WYH + k*48 + o] = W1y[o*104 + k];
        sm[W2P + k*48 + o] = W2p[idx];
        sm[W2F + k*48 + o] = W2f[idx];
        sm[W2Y + k*48 + o] = W2y[idx];
    }
    for (int idx = tid; idx < 48*72; idx += TPB) {
        int k = idx/72, p = idx - k*72;
        float* d = &sm[WG + idx*4];
        d[0] = Wih[(2*p)*48 + k]; d[1] = Wih[(2*p+1)*48 + k];
        d[2] = Whh[(2*p)*48 + k]; d[3] = Whh[(2*p+1)*48 + k];
    }
    for (int idx = tid; idx < 48*8; idx += TPB) {
        int o = idx/8, k = idx - o*8;
        sm[WPM + k*48 + o] = W1p[o*104 + 96 + k];
        sm[WFM + k*48 + o] = W1f[o*104 + 96 + k];
        sm[WYM + k*48 + o] = W1y[o*104 + 96 + k];
    }
    for (int idx = tid; idx < 384; idx += TPB) sm[WDEC+idx]=Wdec[idx];
    if (tid < 48) { sm[B1P+tid]=b1p[tid]; sm[B1F+tid]=b1f[tid]; }
    for (int idx = tid; idx < 144; idx += TPB) { sm[BIH+idx]=bih[idx]; sm[BHH+idx]=bhh[idx]; }
    if (tid < 8) sm[BDEC+tid]=bdec[tid];

    // state init: hsh, halos, xsh = H^T y, hy -> buf1 (temp)
    for (int idx = tid; idx < 48*128; idx += TPB) {
        int k = idx >> 7, cc = idx & 127; int t = t0 + cc;
        buf0[idx] = (t < Tn) ? hx0[(b*48+k)*Tn + t] : 0.f;
    }
    if (tid < 48) {
        int tl = t0 - 1, tr = t0 + 128;
        sm[HLo+tid] = (tl >= 0) ? hx0[(b*48+tid)*Tn + tl] : 0.f;
        sm[HRo+tid] = (tr < Tn) ? hx0[(b*48+tid)*Tn + tr] : 0.f;
    }
    for (int idx = tid; idx < 8*130; idx += TPB) {
        int k = idx / 130, cc = idx - k*130; int t = t0 + cc - 1;
        float v = 0.f;
        if (t >= 0 && t < Tn) {
            const float* yp = &ys[((size_t)b*Tn + t)*4];
            #pragma unroll
            for (int y = 0; y < 4; y++) v = fmaf(Hm[y*8+k], yp[y], v);
        }
        xsh[idx] = v;
    }
    for (int idx = tid; idx < 48*128; idx += TPB) {
        int o = idx >> 7, cc = idx & 127; int t = t0 + cc;
        float s = 0.f;
        if (t < Tn) {
            const float* yp = &ys[((size_t)b*Tn + t)*4];
            s = b_hy[o];
            #pragma unroll
            for (int y = 0; y < 4; y++) s = fmaf(W_hy[o*4+y], yp[y], s);
        }
        buf1[idx] = s;   // hy (temp)
    }
    __syncthreads();

    const int w = tid >> 5, lane = tid & 31, cg = w & 1, rg = w >> 1;
    const int rbase = 6*rg, cbase = cg*64 + 2*lane;
    const int inv = Tn - t0;

    // per-thread cy registers (HtRi parked at MPo)
    float cy0 = 0.f, cy1 = 0.f;
    {
        int i0 = tid >> 7, n0 = tid & 127, ta = t0 + n0;
        if (ta < Tn) {
            const float* yp = &ys[((size_t)b*Tn + ta)*4];
            #pragma unroll
            for (int y = 0; y < 4; y++) cy0 = fmaf(sm[MPo+i0*4+y], yp[y], cy0);
        }
        int i1 = (tid+TPB) >> 7, n1 = (tid+TPB) & 127, tb = t0 + n1;
        if (tb < Tn) {
            const float* yp = &ys[((size_t)b*Tn + tb)*4];
            #pragma unroll
            for (int y = 0; y < 4; y++) cy1 = fmaf(sm[MPo+i1*4+y], yp[y], cy1);
        }
    }

    // yterm registers from hy (in buf1)
    ull ytr0[3], ytr1[3];
    #pragma unroll
    for (int p = 0; p < 3; p++) {
        int o0 = rbase + 2*p, o1 = o0 + 1;
        float a0=0.f, a1=0.f, b0v=0.f, b1v=0.f;
        if (t0 + cbase < Tn) {
            a0 = b1y[o0]; a1 = b1y[o1];
            for (int k = 0; k < 48; k++) {
                float hv = buf1[k*128 + cbase];
                a0 = fmaf(W1y[o0*104+48+k], hv, a0);
                a1 = fmaf(W1y[o1*104+48+k], hv, a1);
            }
        }
        if (t0 + cbase + 1 < Tn) {
            b0v = b1y[o0]; b1v = b1y[o1];
            for (int k = 0; k < 48; k++) {
                float hv = buf1[k*128 + cbase + 1];
                b0v = fmaf(W1y[o0*104+48+k], hv, b0v);
                b1v = fmaf(W1y[o1*104+48+k], hv, b1v);
            }
        }
        ytr0[p] = pack2(a0, a1);
        ytr1[p] = pack2(b0v, b1v);
    }
    __syncthreads();

    // prologue messages (it=0, halos fresh)
    msgphase(sm, xsh, t0, tid, cy0, cy1);
    __syncthreads();

    // ================= MAIN LOOP =================
    for (int it = 0; it < iters; it++) {
        float* hcur  = (it & 1) ? buf1 : buf0;
        float* hnext = (it & 1) ? buf0 : buf1;
        const float* lsrc; int lstr; const float* rsrc; int rstr;
        if (cg == 0) { lsrc = sm+HLo; lstr = 1; rsrc = hcur+64; rstr = 128; }
        else         { lsrc = hcur+63; lstr = 128; rsrc = sm+HRo; rstr = 1; }

        ull agg[3][2];
        #pragma unroll
        for (int p = 0; p < 3; p++) {
            ull bp = *(const ull*)&sm[B2S + rbase + 2*p];
            agg[p][0] = bp; agg[p][1] = bp;
        }
        // B: edge_p -> hnext
        {
            ull acc[3][2];
            #pragma unroll
            for (int p = 0; p < 3; p++) { ull bp = *(const ull*)&sm[B1P+rbase+2*p]; acc[p][0]=bp; acc[p][1]=bp; }
            edge1pf<-1>(sm, WEP, WPM, sm+MPo, hcur, hnext, acc, rg, rbase, lane, cbase, lsrc, lstr, rsrc, rstr);
        }
        __syncthreads();
        // C: layer2p(hnext) ; edge_f -> scr
        layer2v(sm, W2P, hnext, agg, rbase, cbase);
        {
            ull acc[3][2];
            #pragma unroll
            for (int p = 0; p < 3; p++) { ull bp = *(const ull*)&sm[B1F+rbase+2*p]; acc[p][0]=bp; acc[p][1]=bp; }
            edge1pf<1>(sm, WEF, WFM, sm+MFo, hcur, scr, acc, rg, rbase, lane, cbase, lsrc, lstr, rsrc, rstr);
        }
        __syncthreads();
        // D: layer2f(scr) ; edge_y -> hnext
        layer2v(sm, W2F, scr, agg, rbase, cbase);
        {
            ull acc[3][2];
            #pragma unroll
            for (int p = 0; p < 3; p++) { acc[p][0] = ytr0[p]; acc[p][1] = ytr1[p]; }
            edge1y(sm, sm+MYo, hcur, hnext, acc, rbase, cbase);
        }
        __syncthreads();
        // E: layer2y(hnext) ; spill agg -> scr
        layer2v(sm, W2Y, hnext, agg, rbase, cbase);
        #pragma unroll
        for (int p = 0; p < 3; p++) {
            float x0,x1,y0,y1;
            unpack2(agg[p][0],x0,y0); unpack2(agg[p][1],x1,y1);
            int o0 = rbase + 2*p;
            scr[o0*128+cbase] = x0;   scr[o0*128+cbase+1] = x1;
            scr[(o0+1)*128+cbase] = y0; scr[(o0+1)*128+cbase+1] = y1;
        }
        __syncthreads();

        // F: GRU
        {
            ull A[9][2], Bv[3][2];
            #pragma unroll
            for (int g = 0; g < 3; g++)
                #pragma unroll
                for (int p = 0; p < 3; p++) {
                    ull bi = *(const ull*)&sm[BIH + g*48 + rbase + 2*p];
                    if (g < 2) bi = add2(bi, *(const ull*)&sm[BHH + g*48 + rbase + 2*p]);
                    A[g*3+p][0] = bi; A[g*3+p][1] = bi;
                }
            #pragma unroll
            for (int p = 0; p < 3; p++) {
                ull bb = *(const ull*)&sm[BHH + 96 + rbase + 2*p];
                Bv[p][0] = bb; Bv[p][1] = bb;
            }
            #pragma unroll 2
            for (int k = 0; k < 48; k++) {
                float2 xv = *(const float2*)&scr[k*128 + cbase];
                float2 hv = *(const float2*)&hcur[k*128 + cbase];
                ull xb0 = pack2(xv.x,xv.x), xb1 = pack2(xv.y,xv.y);
                ull hb0 = pack2(hv.x,hv.x), hb1 = pack2(hv.y,hv.y);
                const ulonglong2* wg = (const ulonglong2*)&sm[WG + k*72*4];
                #pragma unroll
                for (int j = 0; j < 3; j++) {
                    ulonglong2 w0 = wg[3*rg + j];
                    A[j][0] = fma2(w0.x, xb0, A[j][0]); A[j][1] = fma2(w0.x, xb1, A[j][1]);
                    A[j][0] = fma2(w0.y, hb0, A[j][0]); A[j][1] = fma2(w0.y, hb1, A[j][1]);
                    ulonglong2 w1 = wg[24 + 3*rg + j];
                    A[3+j][0] = fma2(w1.x, xb0, A[3+j][0]); A[3+j][1] = fma2(w1.x, xb1, A[3+j][1]);
                    A[3+j][0] = fma2(w1.y, hb0, A[3+j][0]); A[3+j][1] = fma2(w1.y, hb1, A[3+j][1]);
                    ulonglong2 w2 = wg[48 + 3*rg + j];
                    A[6+j][0] = fma2(w2.x, xb0, A[6+j][0]); A[6+j][1] = fma2(w2.x, xb1, A[6+j][1]);
                    Bv[j][0]  = fma2(w2.y, hb0, Bv[j][0]);  Bv[j][1]  = fma2(w2.y, hb1, Bv[j][1]);
                }
            }
            #pragma unroll
            for (int p = 0; p < 3; p++)
                #pragma unroll
                for (int cc2 = 0; cc2 < 2; cc2++) {
                    float rv0,rv1,zv0,zv1,nv0,nv1,bn0,bn1;
                    unpack2(A[p][cc2],rv0,rv1); unpack2(A[3+p][cc2],zv0,zv1);
                    unpack2(A[6+p][cc2],nv0,nv1); unpack2(Bv[p][cc2],bn0,bn1);
                    int cc = cbase + cc2;
                    int o0 = rbase + 2*p, o1 = o0 + 1;
                    float rr0 = sigmf(rv0), rr1 = sigmf(rv1);
                    float zz0 = sigmf(zv0), zz1 = sigmf(zv1);
                    float ng0 = tanhfast(nv0 + rr0*bn0), ng1 = tanhfast(nv1 + rr1*bn1);
                    float h0 = hcur[o0*128 + cc], h1 = hcur[o1*128 + cc];
                    hnext[o0*128+cc] = (1.f-zz0)*ng0 + zz0*h0;
                    hnext[o1*128+cc] = (1.f-zz1)*ng1 + zz1*h1;
                }
        }
        __syncthreads();

        // G: shift-leak guard, publish, decoder
        const int par = it & 1;
        if (inv < 128 && tid < 48) hnext[tid*128 + inv] = 0.f;
        if (tid < 48) {
            g_hh[par][b][c][0][tid] = hnext[tid*128 + 0];
            int t127 = t0 + 127;
            g_hh[par][b][c][1][tid] = (t127 < Tn) ? hnext[tid*128 + 127] : 0.f;
        }
        {
            float* outp = out + (size_t)BXT * (1 + it);
            bool last = (it == iters - 1);
            #pragma unroll
            for (int rep = 0; rep < 2; rep++) {
                int item = tid + rep*TPB;
                int i = item >> 7, n = item & 127, t = t0 + n;
                float e = sm[BDEC+i];
                #pragma unroll 8
                for (int k = 0; k < 48; k++) e = fmaf(sm[WDEC+i*48+k], hnext[k*128+n], e);
                float xn = 0.f;
                if (t < Tn) {
                    xn = xsh[i*130 + 1 + n]
                       + GAMMA_F * (e + sm[MPo+i*128+n] + sm[MFo+i*128+n] + sm[MYo+i*128+n]);
                    xsh[i*130 + 1 + n] = xn;
                    outp[(b*8+i)*Tn + t] = xn;
                    if (last) out[(b*8+i)*Tn + t] = xn;
                }
                if (n == 0)   g_xh[par][b][c][0][i] = xn;
                if (n == 127) g_xh[par][b][c][1][i] = xn;
            }
        }
        __syncthreads();   // all publishes done

        if (it + 1 < iters) {
            const unsigned tgt = base + (unsigned)it + 1u;
            // release: publish progress
            if (tid == 0) {
                __threadfence();
                g_flag[b][c*32] = tgt;
            }
            // barrier-shadow work: interior messages for next iteration
            msgphase(sm, xsh, t0, tid, cy0, cy1);
            // acquire: wait for neighbors
            if (tid == 0 && c > 0) {
                while (g_flag[b][(c-1)*32] < tgt) { __nanosleep(32); }
                __threadfence();
            }
            if (tid == 32 && c < NCHUNK-1) {
                while (g_flag[b][(c+1)*32] < tgt) { __nanosleep(32); }
                __threadfence();
            }
            __syncthreads();
            // pull halos, fix boundary messages
            if (tid < 48) {
                sm[HLo+tid] = (c > 0) ? g_hh[par][b][c-1][1][tid] : 0.f;
            } else if (tid < 96) {
                int k = tid-48;
                sm[HRo+k] = (c < NCHUNK-1) ? g_hh[par][b][c+1][0][k] : 0.f;
            } else if (tid < 104) {
                int i = tid-96;
                float a = 0.f;
                if (c > 0) {
                    const float* xl = g_xh[par][b][c-1][1];
                    #pragma unroll
                    for (int j = 0; j < 8; j++)
                        a += -sm[SQI+i*8+j]*xsh[j*130+1] + sm[SQIF+i*8+j]*xl[j];
                }
                sm[MPo + i*128 + 0] = a;
            } else if (tid < 112) {
                int i = tid-104;
                float a = 0.f;
                if (c < NCHUNK-1) {
                    const float* xr = g_xh[par][b][c+1][0];
                    #pragma unroll
                    for (int j = 0; j < 8; j++)
                        a += sm[SFTQI+i*8+j]*xr[j] - sm[SFTQIF+i*8+j]*xsh[j*130+128];
                }
                sm[MFo + i*128 + 127] = a;
            }
            __syncthreads();
        }
    }
}

extern "C" void kernel_launch(void* const* d_in, const int* in_sizes, int n_in,
                              void* d_out, int out_size) {
    const float* ys   = (const float*)d_in[0];
    const float* hx0  = (const float*)d_in[1];
    const float* F    = (const float*)d_in[2];
    const float* H    = (const float*)d_in[3];
    const float* Q    = (const float*)d_in[4];
    const float* R    = (const float*)d_in[5];
    const float* W_hy = (const float*)d_in[6];
    const float* b_hy = (const float*)d_in[7];
    const float* W1p  = (const float*)d_in[8];
    const float* b1p  = (const float*)d_in[9];
    const float* W2p  = (const float*)d_in[10];
    const float* b2p  = (const float*)d_in[11];
    const float* W1f  = (const float*)d_in[12];
    const float* b1f  = (const float*)d_in[13];
    const float* W2f  = (const float*)d_in[14];
    const float* b2f  = (const float*)d_in[15];
    const float* W1y  = (const float*)d_in[16];
    const float* b1y  = (const float*)d_in[17];
    const float* W2y  = (const float*)d_in[18];
    const float* b2y  = (const float*)d_in[19];
    const float* Wih  = (const float*)d_in[20];
    const float* bih  = (const float*)d_in[21];
    const float* Whh  = (const float*)d_in[22];
    const float* bhh  = (const float*)d_in[23];
    const float* Wdec = (const float*)d_in[24];
    const float* bdec = (const float*)d_in[25];
    float* out = (float*)d_out;

    const int iters = out_size / BXT - 1;

    cudaFuncSetAttribute(persist_kernel, cudaFuncAttributeMaxDynamicSharedMemorySize, SMEM_BYTES);

    dim3 grid(NCHUNK, Bn);
    persist_kernel<<<grid, TPB, SMEM_BYTES>>>(ys, hx0, F, H, Q, R, W_hy, b_hy,
        out, iters,
        W1p, b1p, W2p, b2p, W1f, b1f, W2f, b2f, W1y, b1y, W2y, b2y,
        Wih, bih, Whh, bhh, Wdec, bdec);
}